// round 13
// baseline (speedup 1.0000x reference)
#include <cuda_runtime.h>
#include <cuda_fp16.h>
#include <math.h>
#include <stdint.h>

// Problem constants: N=512, H=64, M=1024, B=256, ETA=1
#define L2E 1.4426950408889634f
#define L2E2 0x3DC53DC5u  // fp16x2(log2 e)

// ---------------------------------------------------------------------------
__device__ __forceinline__ uint32_t smem_u32(const void* p) {
    uint32_t a;
    asm("{ .reg .u64 t; cvta.to.shared.u64 t, %1; cvt.u32.u64 %0, t; }" : "=r"(a) : "l"(p));
    return a;
}
__device__ __forceinline__ void ldsm_x4(uint32_t r[4], uint32_t addr) {
    asm volatile("ldmatrix.sync.aligned.m8n8.x4.shared.b16 {%0,%1,%2,%3}, [%4];"
                 : "=r"(r[0]), "=r"(r[1]), "=r"(r[2]), "=r"(r[3]) : "r"(addr));
}
__device__ __forceinline__ void ldsm_x4t(uint32_t r[4], uint32_t addr) {
    asm volatile("ldmatrix.sync.aligned.m8n8.x4.trans.shared.b16 {%0,%1,%2,%3}, [%4];"
                 : "=r"(r[0]), "=r"(r[1]), "=r"(r[2]), "=r"(r[3]) : "r"(addr));
}
__device__ __forceinline__ void mma_f16acc(uint32_t c[2], const uint32_t a[4],
                                           uint32_t b0, uint32_t b1) {
    asm volatile("mma.sync.aligned.m16n8k16.row.col.f16.f16.f16.f16 "
                 "{%0,%1}, {%2,%3,%4,%5}, {%6,%7}, {%0,%1};"
                 : "+r"(c[0]), "+r"(c[1])
                 : "r"(a[0]), "r"(a[1]), "r"(a[2]), "r"(a[3]), "r"(b0), "r"(b1));
}
__device__ __forceinline__ uint32_t packhf(float lo, float hi) {
    uint32_t d;
    asm("cvt.rn.f16x2.f32 %0, %1, %2;" : "=r"(d) : "f"(hi), "f"(lo));
    return d;
}
__device__ __forceinline__ uint32_t mul_f16x2(uint32_t a, uint32_t b) {
    uint32_t d; asm("mul.rn.f16x2 %0, %1, %2;" : "=r"(d) : "r"(a), "r"(b)); return d;
}
__device__ __forceinline__ uint32_t fma_f16x2(uint32_t a, uint32_t b, uint32_t c) {
    uint32_t d; asm("fma.rn.f16x2 %0, %1, %2, %3;" : "=r"(d) : "r"(a), "r"(b), "r"(c)); return d;
}
__device__ __forceinline__ uint32_t add_f16x2(uint32_t a, uint32_t b) {
    uint32_t d; asm("add.rn.f16x2 %0, %1, %2;" : "=r"(d) : "r"(a), "r"(b)); return d;
}
__device__ __forceinline__ uint32_t ex2_f16x2(uint32_t a) {
    uint32_t d; asm("ex2.approx.f16x2 %0, %1;" : "=r"(d) : "r"(a)); return d;
}
__device__ __forceinline__ float2 unpack_hf(uint32_t v) {
    __half2 h = *(__half2*)&v; return __half22float2(h);
}
__device__ __forceinline__ void cp16(uint32_t dst, const void* src) {
    uint64_t g;
    asm("cvta.to.global.u64 %0, %1;" : "=l"(g) : "l"(src));
    asm volatile("cp.async.ca.shared.global [%0], [%1], 16;" :: "r"(dst), "l"(g));
}
#define CP_COMMIT() asm volatile("cp.async.commit_group;" ::: "memory")
#define CP_WAIT(n)  asm volatile("cp.async.wait_group %0;" :: "n"(n) : "memory")

// ---------------------------------------------------------------------------
// Scratch
__device__ float  g_Bn[64 * 512];
__device__ __align__(16) __half g_phiF[64 * 1024];    // phi fp16 [h][m]
__device__ __align__(16) uint32_t g_seqhf[256 * 256]; // seq fp16 [b][512]
__device__ double g_acc;
__device__ int    g_ctr;
__device__ int    g_work;

// ---------------------------------------------------------------------------
__global__ void k_bn(const float* __restrict__ Blog) {
    int h = blockIdx.x, l = threadIdx.x;
    if (h == 0 && l == 0) { g_acc = 0.0; g_ctr = 0; g_work = 0; }
    const float* row = Blog + h * 512;
    float x[16];
    float mx = -3.402823466e38f;
#pragma unroll
    for (int k = 0; k < 16; k++) { x[k] = row[l + k * 32]; mx = fmaxf(mx, x[k]); }
#pragma unroll
    for (int o = 16; o; o >>= 1) mx = fmaxf(mx, __shfl_xor_sync(0xffffffffu, mx, o));
    float s = 0.f;
#pragma unroll
    for (int k = 0; k < 16; k++) { x[k] = exp2f((x[k] - mx) * L2E); s += x[k]; }
#pragma unroll
    for (int o = 16; o; o >>= 1) s += __shfl_xor_sync(0xffffffffu, s, o);
    float inv = 1.0f / s;
#pragma unroll
    for (int k = 0; k < 16; k++) g_Bn[h * 512 + l + k * 32] = x[k] * inv;
}

// phi GEMM -> fp16 [h][m]; blocks 0-255 also pack seq to fp16
__global__ void k_phi(const float* __restrict__ mem, const float* __restrict__ seq) {
    __shared__ float row[512];
    int m = blockIdx.x, tid = threadIdx.x;
    if (m < 256) {
        int idx = m * 128 + tid;
        float4 v = ((const float4*)seq)[idx];
        uint2 o;
        o.x = packhf(v.x, v.y);
        o.y = packhf(v.z, v.w);
        ((uint2*)g_seqhf)[idx] = o;
    }
    for (int i = tid; i < 512; i += 128) row[i] = mem[m * 512 + i];
    __syncthreads();
    int w = tid >> 5, l = tid & 31;
#pragma unroll 4
    for (int hh = 0; hh < 16; hh++) {
        int h = w * 16 + hh;
        float a = 0.f;
#pragma unroll
        for (int k = 0; k < 16; k++) { int i = l + k * 32; a += g_Bn[h * 512 + i] * row[i]; }
#pragma unroll
        for (int o = 16; o; o >>= 1) a += __shfl_xor_sync(0xffffffffu, a, o);
        if (l == 0) g_phiF[h * 1024 + m] = __float2half(a);
    }
}

// ---------------------------------------------------------------------------
// PERSISTENT FUSED kernel: work-stealing over n (largest first). Per n:
// hat GEMM (f16 acc, f16x2-ex2 weights) -> f16x2 Z-normalize -> score GEMM
// (f16 acc) -> f16x2 exp epilogue -> BCE.
#define SM_RED   0
#define SM_INVZ  256
#define SM_PLUS  512
#define SM_WIDX  2548
#define SM_DYN   2560
// hat buffers: W [32i][64h] fp16 pitch 144 (4608B); S [256b][32i] fp16 pitch 80 (20480B)
#define HB_W 0
#define HB_S 4608
#define HB_STRIDE 25088
// score buffers (x3): phi [64h][128m] fp16 pitch 272 (17408B)
#define PB_STRIDE 17408
#define SM_TOTAL (SM_DYN + 3 * PB_STRIDE)

#define GRID_PERSIST 304

struct HatSt { float4 a0, a1; uint4 s[4]; };

__device__ __forceinline__ void hat_ldg(HatSt& st, const float* __restrict__ Alog,
                                        int n_pos, int hh, int ig, int i0, int tid) {
    const float4* ap = (const float4*)(Alog + (size_t)(n_pos * 64 + hh) * 512 + i0 + ig * 8);
    st.a0 = ap[0]; st.a1 = ap[1];
    const uint4* sp = (const uint4*)g_seqhf + tid * 64 + (i0 >> 3);
#pragma unroll
    for (int u = 0; u < 4; u++) st.s[u] = sp[u];
}

// f16x2 exp weight staging: 1 MUFU per 2 weights, Z accumulated from the
// STORED (masked, f16) values for exact hat/Z consistency.
__device__ __forceinline__ void hat_sts(const HatSt& st, char* sm, int buf,
                                        int n_pos, int hh, int ig, int i0, int tid,
                                        float& zpart) {
    char* base = sm + SM_DYN + buf * HB_STRIDE;
    uint4* d = (uint4*)(base + HB_S + tid * 80);
#pragma unroll
    for (int u = 0; u < 4; u++) d[u] = st.s[u];
    float vv[8] = { st.a0.x, st.a0.y, st.a0.z, st.a0.w,
                    st.a1.x, st.a1.y, st.a1.z, st.a1.w };
#pragma unroll
    for (int j = 0; j < 8; j += 2) {
        int i = i0 + ig * 8 + j;
        uint32_t v2 = packhf(vv[j], vv[j + 1]);
        uint32_t w2 = ex2_f16x2(mul_f16x2(v2, L2E2));
        if (i + 1 >= n_pos) w2 = (i >= n_pos) ? 0u : (w2 & 0xFFFFu);
        float2 wf = unpack_hf(w2);
        zpart += wf.x + wf.y;
        uint32_t whi = w2 >> 16;
        *(uint16_t*)(base + HB_W + (ig * 8 + j) * 144 + hh * 2) = (uint16_t)w2;
        *(uint16_t*)(base + HB_W + (ig * 8 + j + 1) * 144 + hh * 2) = (uint16_t)whi;
    }
}

__device__ __forceinline__ void score_prefetch(uint32_t dynb, int c, int buf, int tid) {
    uint32_t base = dynb + buf * PB_STRIDE;
#pragma unroll
    for (int it = 0; it < 4; it++) {
        int idx = it * 256 + tid;
        int r = idx >> 4, q = idx & 15;
        cp16(base + r * 272 + q * 16, g_phiF + r * 1024 + c * 128 + q * 8);
    }
    CP_COMMIT();
}

__global__ void __launch_bounds__(256, 2) k_fused(const float* __restrict__ Alog,
                                                  const float* __restrict__ seq,
                                                  const float* __restrict__ mem,
                                                  float* __restrict__ out) {
    extern __shared__ char sm[];
    int tid = threadIdx.x, wid = tid >> 5, ln = tid & 31;

    float*    red     = (float*)(sm + SM_RED);
    float*    invZ_s  = (float*)(sm + SM_INVZ);
    uint32_t* plus2_s = (uint32_t*)(sm + SM_PLUS);
    int*      s_widx  = (int*)(sm + SM_WIDX);
    uint32_t  dynb    = smem_u32(sm + SM_DYN);

    for (;;) {
        if (tid == 0) *s_widx = atomicAdd(&g_work, 1);
        __syncthreads();
        int idx = *s_widx;
        __syncthreads();
        if (idx >= 511) break;
        int n_idx = 510 - idx, n_pos = n_idx + 1;

#pragma unroll
        for (int q = 0; q < 2; q++) {
            int mp = q * 256 + tid;  // m pair 0..511
            float p0 = (mem[(size_t)(2 * mp) * 512 + n_pos] > 0.0f) ? 1.0f : 0.0f;
            float p1 = (mem[(size_t)(2 * mp + 1) * 512 + n_pos] > 0.0f) ? 1.0f : 0.0f;
            plus2_s[mp] = packhf(p0, p1);
        }

        // ====================== HAT PHASE (f16 acc) ========================
        uint32_t C2[2][8][2];
#pragma unroll
        for (int mi = 0; mi < 2; mi++)
#pragma unroll
            for (int j = 0; j < 8; j++) { C2[mi][j][0] = 0u; C2[mi][j][1] = 0u; }

        int hh = tid >> 2, ig = tid & 3;
        float zpart = 0.f;
        int nch = (n_pos + 31) >> 5;

        HatSt st;
        hat_ldg(st, Alog, n_pos, hh, ig, 0, tid);
        hat_sts(st, sm, 0, n_pos, hh, ig, 0, tid, zpart);
        __syncthreads();
        if (nch > 1) hat_ldg(st, Alog, n_pos, hh, ig, 32, tid);

        for (int kc = 0; kc < nch; kc++) {
            uint32_t Bb = dynb + (kc & 1) * HB_STRIDE;
#pragma unroll
            for (int ks = 0; ks < 2; ks++) {
                uint32_t aS[2][4];
#pragma unroll
                for (int mi = 0; mi < 2; mi++)
                    ldsm_x4(aS[mi], Bb + HB_S + (wid * 32 + mi * 16 + (ln & 15)) * 80 +
                                     ks * 32 + (ln >> 4) * 16);
#pragma unroll
                for (int nt = 0; nt < 4; nt++) {
                    uint32_t wF[4];
                    uint32_t off = (ks * 16 + (ln & 15)) * 144 +
                                   (nt * 16 + (ln >> 4) * 8) * 2;
                    ldsm_x4t(wF, Bb + HB_W + off);
#pragma unroll
                    for (int mi = 0; mi < 2; mi++) {
                        mma_f16acc(C2[mi][nt * 2 + 0], aS[mi], wF[0], wF[1]);
                        mma_f16acc(C2[mi][nt * 2 + 1], aS[mi], wF[2], wF[3]);
                    }
                }
            }
            if (kc + 1 < nch)
                hat_sts(st, sm, (kc + 1) & 1, n_pos, hh, ig, (kc + 1) * 32, tid, zpart);
            __syncthreads();
            if (kc + 2 < nch) hat_ldg(st, Alog, n_pos, hh, ig, (kc + 2) * 32, tid);
        }

        // Z reduce (4 lanes per h) and f16x2 normalize
        zpart += __shfl_xor_sync(0xffffffffu, zpart, 1);
        zpart += __shfl_xor_sync(0xffffffffu, zpart, 2);
        if ((tid & 3) == 0) invZ_s[hh] = 1.0f / zpart;
        __syncthreads();

#pragma unroll
        for (int j = 0; j < 8; j++) {
            int h0 = j * 8 + 2 * (ln & 3);
            uint32_t iz2 = packhf(invZ_s[h0], invZ_s[h0 + 1]);
#pragma unroll
            for (int mi = 0; mi < 2; mi++) {
                C2[mi][j][0] = mul_f16x2(C2[mi][j][0], iz2);
                C2[mi][j][1] = mul_f16x2(C2[mi][j][1], iz2);
            }
        }

        // f16-acc C-frags are directly score A-frags
        uint32_t aF[2][4][4];
#pragma unroll
        for (int mi = 0; mi < 2; mi++)
#pragma unroll
            for (int kj = 0; kj < 4; kj++) {
                aF[mi][kj][0] = C2[mi][2 * kj][0];
                aF[mi][kj][1] = C2[mi][2 * kj][1];
                aF[mi][kj][2] = C2[mi][2 * kj + 1][0];
                aF[mi][kj][3] = C2[mi][2 * kj + 1][1];
            }

        // ============ SCORE PHASE (f16 acc, cp.async 3-buffer ring) ========
        float num[2][2] = {{0.f, 0.f}, {0.f, 0.f}};
        float den[2][2] = {{0.f, 0.f}, {0.f, 0.f}};

        score_prefetch(dynb, 0, 0, tid);
        score_prefetch(dynb, 1, 1, tid);

        for (int c = 0; c < 8; c++) {
            if (c < 7) CP_WAIT(1); else CP_WAIT(0);
            __syncthreads();
            if (c + 2 < 8) score_prefetch(dynb, c + 2, (c + 2) % 3, tid);

            uint32_t Pb = dynb + (c % 3) * PB_STRIDE;
            uint32_t num2[2][2] = {{0u, 0u}, {0u, 0u}};
            uint32_t den2[2][2] = {{0u, 0u}, {0u, 0u}};
#pragma unroll
            for (int pr = 0; pr < 8; pr++) {
                uint32_t cc[2][2][2];
#pragma unroll
                for (int mi = 0; mi < 2; mi++)
#pragma unroll
                    for (int t2 = 0; t2 < 2; t2++) { cc[mi][t2][0] = 0u; cc[mi][t2][1] = 0u; }

#pragma unroll
                for (int kj = 0; kj < 4; kj++) {
                    uint32_t bF[4];
                    uint32_t off = (kj * 16 + (ln & 15)) * 272 +
                                   (pr * 16 + (ln >> 4) * 8) * 2;
                    ldsm_x4t(bF, Pb + off);
#pragma unroll
                    for (int mi = 0; mi < 2; mi++) {
                        mma_f16acc(cc[mi][0], aF[mi][kj], bF[0], bF[1]);
                        mma_f16acc(cc[mi][1], aF[mi][kj], bF[2], bF[3]);
                    }
                }
#pragma unroll
                for (int t2 = 0; t2 < 2; t2++) {
                    uint32_t p2 = plus2_s[c * 64 + pr * 8 + t2 * 4 + (ln & 3)];
#pragma unroll
                    for (int mi = 0; mi < 2; mi++) {
#pragma unroll
                        for (int r2 = 0; r2 < 2; r2++) {
                            uint32_t e = ex2_f16x2(mul_f16x2(cc[mi][t2][r2], L2E2));
                            den2[mi][r2] = add_f16x2(den2[mi][r2], e);
                            num2[mi][r2] = fma_f16x2(e, p2, num2[mi][r2]);
                        }
                    }
                }
            }
#pragma unroll
            for (int mi = 0; mi < 2; mi++) {
#pragma unroll
                for (int r2 = 0; r2 < 2; r2++) {
                    float2 dd = unpack_hf(den2[mi][r2]);
                    float2 nn = unpack_hf(num2[mi][r2]);
                    den[mi][r2] += dd.x + dd.y;
                    num[mi][r2] += nn.x + nn.y;
                }
            }
            __syncthreads();
        }

        // reduce over the 4 lanes sharing each row
#pragma unroll
        for (int o = 1; o <= 2; o <<= 1) {
#pragma unroll
            for (int mi = 0; mi < 2; mi++)
#pragma unroll
                for (int ri = 0; ri < 2; ri++) {
                    num[mi][ri] += __shfl_xor_sync(0xffffffffu, num[mi][ri], o);
                    den[mi][ri] += __shfl_xor_sync(0xffffffffu, den[mi][ri], o);
                }
        }
        if ((ln & 3) == 0) {
            int r = ln >> 2;
            float bce = 0.f;
#pragma unroll
            for (int mi = 0; mi < 2; mi++) {
#pragma unroll
                for (int ri = 0; ri < 2; ri++) {
                    int b = wid * 32 + mi * 16 + ri * 8 + r;
                    float prob = num[mi][ri] / den[mi][ri];
                    prob = fminf(fmaxf(prob, 1e-6f), 1.0f - 1e-6f);
                    bool t = seq[b * 512 + n_pos] > 0.0f;
                    bce += t ? -logf(prob) : -log1pf(-prob);
                }
            }
            red[wid * 8 + r] = bce;
        }
        __syncthreads();
        if (tid == 0) {
            double s = 0.0;
#pragma unroll
            for (int i = 0; i < 64; i++) s += (double)red[i];
            atomicAdd(&g_acc, s);
            __threadfence();
            int done = atomicAdd(&g_ctr, 1);
            if (done == 510) {
                double total = atomicAdd(&g_acc, 0.0);
                out[0] = (float)(total * (1.0 / (256.0 * 511.0)));
            }
        }
        __syncthreads();
    }
}

// ---------------------------------------------------------------------------
extern "C" void kernel_launch(void* const* d_in, const int* in_sizes, int n_in,
                              void* d_out, int out_size) {
    const float *seq = 0, *mem = 0, *Al = 0, *Bl = 0;
    for (int i = 0; i < n_in; i++) {
        switch (in_sizes[i]) {
            case 131072:   seq = (const float*)d_in[i]; break;  // (256,512)
            case 524288:   mem = (const float*)d_in[i]; break;  // (1024,512)
            case 16777216: Al  = (const float*)d_in[i]; break;  // (512,64,512)
            case 32768:    Bl  = (const float*)d_in[i]; break;  // (64,512)
        }
    }
    if (!seq) seq = (const float*)d_in[0];
    if (!mem) mem = (const float*)d_in[1];
    if (!Al)  Al  = (const float*)d_in[2];
    if (!Bl)  Bl  = (const float*)d_in[3];

    cudaFuncSetAttribute(k_fused, cudaFuncAttributeMaxDynamicSharedMemorySize, SM_TOTAL);

    k_bn<<<64, 32>>>(Bl);
    k_phi<<<1024, 128>>>(mem, seq);
    k_fused<<<GRID_PERSIST, 256, SM_TOTAL>>>(Al, seq, mem, (float*)d_out);
}

// round 14
// speedup vs baseline: 1.0793x; 1.0793x over previous
#include <cuda_runtime.h>
#include <cuda_fp16.h>
#include <math.h>
#include <stdint.h>

// Problem constants: N=512, H=64, M=1024, B=256, ETA=1
#define L2E 1.4426950408889634f
#define L2E2 0x3DC53DC5u  // fp16x2(log2 e)

// ---------------------------------------------------------------------------
__device__ __forceinline__ uint32_t smem_u32(const void* p) {
    uint32_t a;
    asm("{ .reg .u64 t; cvta.to.shared.u64 t, %1; cvt.u32.u64 %0, t; }" : "=r"(a) : "l"(p));
    return a;
}
__device__ __forceinline__ void ldsm_x4(uint32_t r[4], uint32_t addr) {
    asm volatile("ldmatrix.sync.aligned.m8n8.x4.shared.b16 {%0,%1,%2,%3}, [%4];"
                 : "=r"(r[0]), "=r"(r[1]), "=r"(r[2]), "=r"(r[3]) : "r"(addr));
}
__device__ __forceinline__ void ldsm_x4t(uint32_t r[4], uint32_t addr) {
    asm volatile("ldmatrix.sync.aligned.m8n8.x4.trans.shared.b16 {%0,%1,%2,%3}, [%4];"
                 : "=r"(r[0]), "=r"(r[1]), "=r"(r[2]), "=r"(r[3]) : "r"(addr));
}
__device__ __forceinline__ void mma_f16acc(uint32_t c[2], const uint32_t a[4],
                                           uint32_t b0, uint32_t b1) {
    asm volatile("mma.sync.aligned.m16n8k16.row.col.f16.f16.f16.f16 "
                 "{%0,%1}, {%2,%3,%4,%5}, {%6,%7}, {%0,%1};"
                 : "+r"(c[0]), "+r"(c[1])
                 : "r"(a[0]), "r"(a[1]), "r"(a[2]), "r"(a[3]), "r"(b0), "r"(b1));
}
__device__ __forceinline__ uint32_t packhf(float lo, float hi) {
    uint32_t d;
    asm("cvt.rn.f16x2.f32 %0, %1, %2;" : "=r"(d) : "f"(hi), "f"(lo));
    return d;
}
__device__ __forceinline__ uint32_t mul_f16x2(uint32_t a, uint32_t b) {
    uint32_t d; asm("mul.rn.f16x2 %0, %1, %2;" : "=r"(d) : "r"(a), "r"(b)); return d;
}
__device__ __forceinline__ uint32_t fma_f16x2(uint32_t a, uint32_t b, uint32_t c) {
    uint32_t d; asm("fma.rn.f16x2 %0, %1, %2, %3;" : "=r"(d) : "r"(a), "r"(b), "r"(c)); return d;
}
__device__ __forceinline__ uint32_t add_f16x2(uint32_t a, uint32_t b) {
    uint32_t d; asm("add.rn.f16x2 %0, %1, %2;" : "=r"(d) : "r"(a), "r"(b)); return d;
}
__device__ __forceinline__ uint32_t ex2_f16x2(uint32_t a) {
    uint32_t d; asm("ex2.approx.f16x2 %0, %1;" : "=r"(d) : "r"(a)); return d;
}
__device__ __forceinline__ float2 unpack_hf(uint32_t v) {
    __half2 h = *(__half2*)&v; return __half22float2(h);
}
__device__ __forceinline__ void cp16(uint32_t dst, const void* src) {
    uint64_t g;
    asm("cvta.to.global.u64 %0, %1;" : "=l"(g) : "l"(src));
    asm volatile("cp.async.ca.shared.global [%0], [%1], 16;" :: "r"(dst), "l"(g));
}
#define CP_COMMIT() asm volatile("cp.async.commit_group;" ::: "memory")
#define CP_WAIT(n)  asm volatile("cp.async.wait_group %0;" :: "n"(n) : "memory")

// ---------------------------------------------------------------------------
// Scratch
__device__ float  g_Bn[64 * 512];
__device__ __align__(16) __half g_phiF[64 * 1024];    // phi fp16 [h][m]
__device__ __align__(16) uint32_t g_seqhf[256 * 256]; // seq fp16 [b][512]
__device__ __align__(16) uint32_t g_hatG[511 * 256 * 32]; // hat f16x2 [n][b][hpair]
__device__ float  g_pnum[511 * 2 * 256];              // partial num [n][half][b]
__device__ float  g_pden[511 * 2 * 256];
__device__ int    g_flag[511];
__device__ double g_acc;
__device__ int    g_ctr;
__device__ int    g_work;

// ---------------------------------------------------------------------------
__global__ void k_bn(const float* __restrict__ Blog) {
    int h = blockIdx.x, l = threadIdx.x;
    int gidx = h * 32 + l;
    if (gidx == 0) { g_acc = 0.0; g_ctr = 0; g_work = 0; }
    if (gidx < 511) g_flag[gidx] = 0;
    const float* row = Blog + h * 512;
    float x[16];
    float mx = -3.402823466e38f;
#pragma unroll
    for (int k = 0; k < 16; k++) { x[k] = row[l + k * 32]; mx = fmaxf(mx, x[k]); }
#pragma unroll
    for (int o = 16; o; o >>= 1) mx = fmaxf(mx, __shfl_xor_sync(0xffffffffu, mx, o));
    float s = 0.f;
#pragma unroll
    for (int k = 0; k < 16; k++) { x[k] = exp2f((x[k] - mx) * L2E); s += x[k]; }
#pragma unroll
    for (int o = 16; o; o >>= 1) s += __shfl_xor_sync(0xffffffffu, s, o);
    float inv = 1.0f / s;
#pragma unroll
    for (int k = 0; k < 16; k++) g_Bn[h * 512 + l + k * 32] = x[k] * inv;
}

// phi GEMM -> fp16 [h][m]; blocks 0-255 also pack seq to fp16
__global__ void k_phi(const float* __restrict__ mem, const float* __restrict__ seq) {
    __shared__ float row[512];
    int m = blockIdx.x, tid = threadIdx.x;
    if (m < 256) {
        int idx = m * 128 + tid;
        float4 v = ((const float4*)seq)[idx];
        uint2 o;
        o.x = packhf(v.x, v.y);
        o.y = packhf(v.z, v.w);
        ((uint2*)g_seqhf)[idx] = o;
    }
    for (int i = tid; i < 512; i += 128) row[i] = mem[m * 512 + i];
    __syncthreads();
    int w = tid >> 5, l = tid & 31;
#pragma unroll 4
    for (int hh = 0; hh < 16; hh++) {
        int h = w * 16 + hh;
        float a = 0.f;
#pragma unroll
        for (int k = 0; k < 16; k++) { int i = l + k * 32; a += g_Bn[h * 512 + i] * row[i]; }
#pragma unroll
        for (int o = 16; o; o >>= 1) a += __shfl_xor_sync(0xffffffffu, a, o);
        if (l == 0) g_phiF[h * 1024 + m] = __float2half(a);
    }
}

// ---------------------------------------------------------------------------
// PERSISTENT FUSED kernel, items = (n, m-half). 1022 items, half-0 first.
// half 0: hat GEMM -> normalize -> store hat frags to gmem + flag -> score m 0..511
// half 1: wait flag -> load hat tile -> score m 512..1023
// Partial num/den written to gmem; k_bce folds halves.
#define SM_INVZ  256
#define SM_PLUS  512
#define SM_WIDX  2548
#define SM_DYN   2560
// hat buffers: W [32i][64h] fp16 pitch 144 (4608B); S [256b][32i] fp16 pitch 80 (20480B)
#define HB_W 0
#define HB_S 4608
#define HB_STRIDE 25088
// score buffers (x3): phi [64h][128m] fp16 pitch 272 (17408B)
#define PB_STRIDE 17408
#define SM_TOTAL (SM_DYN + 3 * PB_STRIDE)

#define GRID_PERSIST 304

struct HatSt { float4 a0, a1; uint4 s[4]; };

__device__ __forceinline__ void hat_ldg(HatSt& st, const float* __restrict__ Alog,
                                        int n_pos, int hh, int ig, int i0, int tid) {
    const float4* ap = (const float4*)(Alog + (size_t)(n_pos * 64 + hh) * 512 + i0 + ig * 8);
    st.a0 = ap[0]; st.a1 = ap[1];
    const uint4* sp = (const uint4*)g_seqhf + tid * 64 + (i0 >> 3);
#pragma unroll
    for (int u = 0; u < 4; u++) st.s[u] = sp[u];
}

__device__ __forceinline__ void hat_sts(const HatSt& st, char* sm, int buf,
                                        int n_pos, int hh, int ig, int i0, int tid,
                                        float& zpart) {
    char* base = sm + SM_DYN + buf * HB_STRIDE;
    uint4* d = (uint4*)(base + HB_S + tid * 80);
#pragma unroll
    for (int u = 0; u < 4; u++) d[u] = st.s[u];
    float vv[8] = { st.a0.x, st.a0.y, st.a0.z, st.a0.w,
                    st.a1.x, st.a1.y, st.a1.z, st.a1.w };
#pragma unroll
    for (int j = 0; j < 8; j += 2) {
        int i = i0 + ig * 8 + j;
        uint32_t v2 = packhf(vv[j], vv[j + 1]);
        uint32_t w2 = ex2_f16x2(mul_f16x2(v2, L2E2));
        if (i + 1 >= n_pos) w2 = (i >= n_pos) ? 0u : (w2 & 0xFFFFu);
        float2 wf = unpack_hf(w2);
        zpart += wf.x + wf.y;
        *(uint16_t*)(base + HB_W + (ig * 8 + j) * 144 + hh * 2) = (uint16_t)w2;
        *(uint16_t*)(base + HB_W + (ig * 8 + j + 1) * 144 + hh * 2) = (uint16_t)(w2 >> 16);
    }
}

__device__ __forceinline__ void score_prefetch(uint32_t dynb, int chunk, int buf, int tid) {
    uint32_t base = dynb + buf * PB_STRIDE;
#pragma unroll
    for (int it = 0; it < 4; it++) {
        int idx = it * 256 + tid;
        int r = idx >> 4, q = idx & 15;
        cp16(base + r * 272 + q * 16, g_phiF + r * 1024 + chunk * 128 + q * 8);
    }
    CP_COMMIT();
}

__global__ void __launch_bounds__(256, 2) k_fused(const float* __restrict__ Alog,
                                                  const float* __restrict__ mem) {
    extern __shared__ char sm[];
    int tid = threadIdx.x, wid = tid >> 5, ln = tid & 31;

    float*    invZ_s  = (float*)(sm + SM_INVZ);
    uint32_t* plus2_s = (uint32_t*)(sm + SM_PLUS);
    int*      s_widx  = (int*)(sm + SM_WIDX);
    uint32_t  dynb    = smem_u32(sm + SM_DYN);

    for (;;) {
        if (tid == 0) *s_widx = atomicAdd(&g_work, 1);
        __syncthreads();
        int item = *s_widx;
        __syncthreads();
        if (item >= 1022) break;
        int half = (item >= 511) ? 1 : 0;
        int n_idx = 510 - (half ? item - 511 : item);
        int n_pos = n_idx + 1;

        // stage plus pairs for this half's 512 m
        {
            int m2 = half * 256 + tid;  // global m-pair
            float p0 = (mem[(size_t)(2 * m2) * 512 + n_pos] > 0.0f) ? 1.0f : 0.0f;
            float p1 = (mem[(size_t)(2 * m2 + 1) * 512 + n_pos] > 0.0f) ? 1.0f : 0.0f;
            plus2_s[tid] = packhf(p0, p1);
        }

        uint32_t aF[2][4][4];

        if (half == 0) {
            // ====================== HAT PHASE (f16 acc) ====================
            uint32_t C2[2][8][2];
#pragma unroll
            for (int mi = 0; mi < 2; mi++)
#pragma unroll
                for (int j = 0; j < 8; j++) { C2[mi][j][0] = 0u; C2[mi][j][1] = 0u; }

            int hh = tid >> 2, ig = tid & 3;
            float zpart = 0.f;
            int nch = (n_pos + 31) >> 5;

            HatSt st;
            hat_ldg(st, Alog, n_pos, hh, ig, 0, tid);
            hat_sts(st, sm, 0, n_pos, hh, ig, 0, tid, zpart);
            __syncthreads();
            if (nch > 1) hat_ldg(st, Alog, n_pos, hh, ig, 32, tid);

            for (int kc = 0; kc < nch; kc++) {
                uint32_t Bb = dynb + (kc & 1) * HB_STRIDE;
#pragma unroll
                for (int ks = 0; ks < 2; ks++) {
                    uint32_t aS[2][4];
#pragma unroll
                    for (int mi = 0; mi < 2; mi++)
                        ldsm_x4(aS[mi], Bb + HB_S + (wid * 32 + mi * 16 + (ln & 15)) * 80 +
                                         ks * 32 + (ln >> 4) * 16);
#pragma unroll
                    for (int nt = 0; nt < 4; nt++) {
                        uint32_t wF[4];
                        uint32_t off = (ks * 16 + (ln & 15)) * 144 +
                                       (nt * 16 + (ln >> 4) * 8) * 2;
                        ldsm_x4t(wF, Bb + HB_W + off);
#pragma unroll
                        for (int mi = 0; mi < 2; mi++) {
                            mma_f16acc(C2[mi][nt * 2 + 0], aS[mi], wF[0], wF[1]);
                            mma_f16acc(C2[mi][nt * 2 + 1], aS[mi], wF[2], wF[3]);
                        }
                    }
                }
                if (kc + 1 < nch)
                    hat_sts(st, sm, (kc + 1) & 1, n_pos, hh, ig, (kc + 1) * 32, tid, zpart);
                __syncthreads();
                if (kc + 2 < nch) hat_ldg(st, Alog, n_pos, hh, ig, (kc + 2) * 32, tid);
            }

            // Z reduce and f16x2 normalize
            zpart += __shfl_xor_sync(0xffffffffu, zpart, 1);
            zpart += __shfl_xor_sync(0xffffffffu, zpart, 2);
            if ((tid & 3) == 0) invZ_s[hh] = 1.0f / zpart;
            __syncthreads();

#pragma unroll
            for (int j = 0; j < 8; j++) {
                int h0 = j * 8 + 2 * (ln & 3);
                uint32_t iz2 = packhf(invZ_s[h0], invZ_s[h0 + 1]);
#pragma unroll
                for (int mi = 0; mi < 2; mi++) {
                    C2[mi][j][0] = mul_f16x2(C2[mi][j][0], iz2);
                    C2[mi][j][1] = mul_f16x2(C2[mi][j][1], iz2);
                }
            }
            // store hat frags to gmem, release flag
            {
                int r0 = wid * 32 + (ln >> 2);
                int hp = ln & 3;
#pragma unroll
                for (int mi = 0; mi < 2; mi++) {
#pragma unroll
                    for (int j = 0; j < 8; j++) {
                        uint32_t* gp = g_hatG +
                            ((size_t)(n_idx * 256 + r0 + mi * 16)) * 32 + j * 4 + hp;
                        gp[0] = C2[mi][j][0];
                        gp[8 * 32] = C2[mi][j][1];
                    }
                }
            }
            __syncthreads();
            if (tid == 0) { __threadfence(); atomicExch(&g_flag[n_idx], 1); }

            // frags
#pragma unroll
            for (int mi = 0; mi < 2; mi++)
#pragma unroll
                for (int kj = 0; kj < 4; kj++) {
                    aF[mi][kj][0] = C2[mi][2 * kj][0];
                    aF[mi][kj][1] = C2[mi][2 * kj][1];
                    aF[mi][kj][2] = C2[mi][2 * kj + 1][0];
                    aF[mi][kj][3] = C2[mi][2 * kj + 1][1];
                }
        } else {
            // =============== LOAD HAT TILE (half 1) ========================
            if (tid == 0) {
                while (atomicAdd(&g_flag[n_idx], 0) == 0) __nanosleep(64);
            }
            __syncthreads();
#pragma unroll
            for (int it = 0; it < 8; it++) {
                int e = it * 256 + tid;
                int r = e >> 3, q = e & 7;
                cp16(dynb + r * 144 + q * 16,
                     g_hatG + ((size_t)(n_idx * 256 + r)) * 32 + q * 4);
            }
            CP_COMMIT();
            CP_WAIT(0);
            __syncthreads();
#pragma unroll
            for (int mi = 0; mi < 2; mi++)
#pragma unroll
                for (int kj = 0; kj < 4; kj++) {
                    uint32_t a4[4];
                    ldsm_x4(a4, dynb + (wid * 32 + mi * 16 + (ln & 15)) * 144 +
                                 kj * 32 + (ln >> 4) * 16);
                    aF[mi][kj][0] = a4[0]; aF[mi][kj][1] = a4[1];
                    aF[mi][kj][2] = a4[2]; aF[mi][kj][3] = a4[3];
                }
            __syncthreads();
        }

        // ============ SCORE PHASE: 4 chunks of 128 m (this half) ===========
        float num[2][2] = {{0.f, 0.f}, {0.f, 0.f}};
        float den[2][2] = {{0.f, 0.f}, {0.f, 0.f}};

        score_prefetch(dynb, half * 4 + 0, 0, tid);
        score_prefetch(dynb, half * 4 + 1, 1, tid);

        for (int c = 0; c < 4; c++) {
            if (c < 3) CP_WAIT(1); else CP_WAIT(0);
            __syncthreads();
            if (c + 2 < 4) score_prefetch(dynb, half * 4 + c + 2, (c + 2) % 3, tid);

            uint32_t Pb = dynb + (c % 3) * PB_STRIDE;
            uint32_t num2[2][2] = {{0u, 0u}, {0u, 0u}};
            uint32_t den2[2][2] = {{0u, 0u}, {0u, 0u}};
#pragma unroll
            for (int pr = 0; pr < 8; pr++) {
                uint32_t cc[2][2][2];
#pragma unroll
                for (int mi = 0; mi < 2; mi++)
#pragma unroll
                    for (int t2 = 0; t2 < 2; t2++) { cc[mi][t2][0] = 0u; cc[mi][t2][1] = 0u; }

#pragma unroll
                for (int kj = 0; kj < 4; kj++) {
                    uint32_t bF[4];
                    uint32_t off = (kj * 16 + (ln & 15)) * 272 +
                                   (pr * 16 + (ln >> 4) * 8) * 2;
                    ldsm_x4t(bF, Pb + off);
#pragma unroll
                    for (int mi = 0; mi < 2; mi++) {
                        mma_f16acc(cc[mi][0], aF[mi][kj], bF[0], bF[1]);
                        mma_f16acc(cc[mi][1], aF[mi][kj], bF[2], bF[3]);
                    }
                }
#pragma unroll
                for (int t2 = 0; t2 < 2; t2++) {
                    uint32_t p2 = plus2_s[c * 64 + pr * 8 + t2 * 4 + (ln & 3)];
#pragma unroll
                    for (int mi = 0; mi < 2; mi++) {
#pragma unroll
                        for (int r2 = 0; r2 < 2; r2++) {
                            uint32_t e = ex2_f16x2(mul_f16x2(cc[mi][t2][r2], L2E2));
                            den2[mi][r2] = add_f16x2(den2[mi][r2], e);
                            num2[mi][r2] = fma_f16x2(e, p2, num2[mi][r2]);
                        }
                    }
                }
            }
#pragma unroll
            for (int mi = 0; mi < 2; mi++) {
#pragma unroll
                for (int r2 = 0; r2 < 2; r2++) {
                    float2 dd = unpack_hf(den2[mi][r2]);
                    float2 nn = unpack_hf(num2[mi][r2]);
                    den[mi][r2] += dd.x + dd.y;
                    num[mi][r2] += nn.x + nn.y;
                }
            }
            __syncthreads();
        }

        // reduce over the 4 lanes sharing each row, write partials
#pragma unroll
        for (int o = 1; o <= 2; o <<= 1) {
#pragma unroll
            for (int mi = 0; mi < 2; mi++)
#pragma unroll
                for (int ri = 0; ri < 2; ri++) {
                    num[mi][ri] += __shfl_xor_sync(0xffffffffu, num[mi][ri], o);
                    den[mi][ri] += __shfl_xor_sync(0xffffffffu, den[mi][ri], o);
                }
        }
        if ((ln & 3) == 0) {
            int r = ln >> 2;
            float* pn = g_pnum + (size_t)(n_idx * 2 + half) * 256;
            float* pd = g_pden + (size_t)(n_idx * 2 + half) * 256;
#pragma unroll
            for (int mi = 0; mi < 2; mi++)
#pragma unroll
                for (int ri = 0; ri < 2; ri++) {
                    int b = wid * 32 + mi * 16 + ri * 8 + r;
                    pn[b] = num[mi][ri];
                    pd[b] = den[mi][ri];
                }
        }
        __syncthreads();
    }
}

// ---------------------------------------------------------------------------
// Fold halves -> prob -> BCE -> global mean.
__global__ void k_bce(const float* __restrict__ seq, float* __restrict__ out) {
    __shared__ float rs[8];
    int n_idx = blockIdx.x, b = threadIdx.x;
    int n_pos = n_idx + 1;
    int wid = b >> 5, ln = b & 31;
    float num = g_pnum[(size_t)(n_idx * 2) * 256 + b] +
                g_pnum[(size_t)(n_idx * 2 + 1) * 256 + b];
    float den = g_pden[(size_t)(n_idx * 2) * 256 + b] +
                g_pden[(size_t)(n_idx * 2 + 1) * 256 + b];
    float prob = fminf(fmaxf(num / den, 1e-6f), 1.0f - 1e-6f);
    bool t = seq[b * 512 + n_pos] > 0.0f;
    float bce = t ? -logf(prob) : -log1pf(-prob);
#pragma unroll
    for (int o = 16; o; o >>= 1) bce += __shfl_xor_sync(0xffffffffu, bce, o);
    if (ln == 0) rs[wid] = bce;
    __syncthreads();
    if (b == 0) {
        double s = 0.0;
#pragma unroll
        for (int i = 0; i < 8; i++) s += (double)rs[i];
        atomicAdd(&g_acc, s);
        __threadfence();
        int done = atomicAdd(&g_ctr, 1);
        if (done == 510) {
            double total = atomicAdd(&g_acc, 0.0);
            out[0] = (float)(total * (1.0 / (256.0 * 511.0)));
        }
    }
}

// ---------------------------------------------------------------------------
extern "C" void kernel_launch(void* const* d_in, const int* in_sizes, int n_in,
                              void* d_out, int out_size) {
    const float *seq = 0, *mem = 0, *Al = 0, *Bl = 0;
    for (int i = 0; i < n_in; i++) {
        switch (in_sizes[i]) {
            case 131072:   seq = (const float*)d_in[i]; break;  // (256,512)
            case 524288:   mem = (const float*)d_in[i]; break;  // (1024,512)
            case 16777216: Al  = (const float*)d_in[i]; break;  // (512,64,512)
            case 32768:    Bl  = (const float*)d_in[i]; break;  // (64,512)
        }
    }
    if (!seq) seq = (const float*)d_in[0];
    if (!mem) mem = (const float*)d_in[1];
    if (!Al)  Al  = (const float*)d_in[2];
    if (!Bl)  Bl  = (const float*)d_in[3];

    cudaFuncSetAttribute(k_fused, cudaFuncAttributeMaxDynamicSharedMemorySize, SM_TOTAL);

    k_bn<<<64, 32>>>(Bl);
    k_phi<<<1024, 128>>>(mem, seq);
    k_fused<<<GRID_PERSIST, 256, SM_TOTAL>>>(Al, mem);
    k_bce<<<511, 256>>>(seq, (float*)d_out);
}